// round 1
// baseline (speedup 1.0000x reference)
#include <cuda_runtime.h>
#include <cstdint>

#define N_NODES 100000
#define N_EDGESC 1600000
#define N_GRAPHS 512
#define DH 128
#define DLAT 64
#define NCOND 7
#define BN_EPS 1e-5f

// ---------------- scratch (device globals; no allocation allowed) ----------------
__device__ float g_agg[N_NODES * DH];
__device__ float g_h[N_NODES * DH];
__device__ float g_x[N_NODES * DH];
__device__ float g_sum[DH];
__device__ float g_sumsq[DH];
__device__ float g_a[DH];
__device__ float g_c[DH];
__device__ float g_pooled[N_GRAPHS * DH];
__device__ float g_pa[DH];
__device__ float g_pc[DH];
__device__ float g_h1[N_GRAPHS * DLAT];
__device__ float g_fa[DLAT];
__device__ float g_fc[DLAT];

// ---------------- helpers ----------------
__device__ __forceinline__ void red_add_v4(float* p, float4 v) {
    asm volatile("red.global.add.v4.f32 [%0], {%1,%2,%3,%4};"
                 :: "l"(p), "f"(v.x), "f"(v.y), "f"(v.z), "f"(v.w) : "memory");
}

__device__ __forceinline__ float leaky(float x) { return fmaxf(x, 0.2f * x); }

// ---------------- zero ----------------
__global__ void zerok(float4* p, int n4) {
    int i = blockIdx.x * blockDim.x + threadIdx.x;
    if (i < n4) p[i] = make_float4(0.f, 0.f, 0.f, 0.f);
}

// ---------------- edge scatter-add: agg[dst] += x[src] ----------------
__global__ void __launch_bounds__(256) edge_agg(const float* __restrict__ x,
                                                const int* __restrict__ src,
                                                const int* __restrict__ dst,
                                                float* __restrict__ agg, int nE) {
    int e = blockIdx.x * 8 + (threadIdx.x >> 5);
    int lane = threadIdx.x & 31;
    if (e >= nE) return;
    int s = __ldg(src + e);
    int d = __ldg(dst + e);
    float4 v = ((const float4*)(x + (size_t)s * DH))[lane];
    red_add_v4(agg + (size_t)d * DH + lane * 4, v);
}

// ---------------- fused GEMM: out = leaky(A' @ W + bias) ----------------
// mode 1: A' = A + A2 (x + agg); also accumulates per-column sum/sumsq of the output
// mode 2: A' = A * affa[k] + affc[k] (folded BatchNorm on the K axis)
__global__ void __launch_bounds__(256) gemm_fused(
    const float* __restrict__ A, const float* __restrict__ A2,
    const float* __restrict__ W, const float* __restrict__ bias,
    const float* __restrict__ affa, const float* __restrict__ affc,
    float* __restrict__ out, float* __restrict__ gsum, float* __restrict__ gsq,
    int M, int mode) {
    extern __shared__ float sm[];
    float* As = sm;            // [128][128]
    float* Ws = sm + 16384;    // [128][128]
    int tid = threadIdx.x;
    int row0 = blockIdx.x << 7;

    // stage W (whole 128x128)
    const float4* Wv = (const float4*)W;
    float4* Wsv = (float4*)Ws;
#pragma unroll
    for (int i = tid; i < 4096; i += 256) Wsv[i] = Wv[i];

    // stage A tile (128 rows x 128 k), fusing (+agg) or BN affine
#pragma unroll
    for (int c = 0; c < 16; c++) {
        int idx = c * 256 + tid;
        int r = idx >> 5;
        int kq = idx & 31;
        int grow = row0 + r;
        float4 v = make_float4(0.f, 0.f, 0.f, 0.f);
        if (grow < M) {
            v = ((const float4*)(A + (size_t)grow * DH))[kq];
            if (mode == 1) {
                float4 w = ((const float4*)(A2 + (size_t)grow * DH))[kq];
                v.x += w.x; v.y += w.y; v.z += w.z; v.w += w.w;
            } else {
                float4 a4 = ((const float4*)affa)[kq];
                float4 c4 = ((const float4*)affc)[kq];
                v.x = v.x * a4.x + c4.x; v.y = v.y * a4.y + c4.y;
                v.z = v.z * a4.z + c4.z; v.w = v.w * a4.w + c4.w;
            }
        }
        ((float4*)As)[idx] = v;
    }
    __syncthreads();

    int tx = tid & 15, ty = tid >> 4;
    float acc[8][8];
#pragma unroll
    for (int i = 0; i < 8; i++)
#pragma unroll
        for (int j = 0; j < 8; j++) acc[i][j] = 0.f;

    const float* Abase = As + (ty * 8) * DH;
#pragma unroll 8
    for (int k = 0; k < DH; k++) {
        float a[8];
#pragma unroll
        for (int i = 0; i < 8; i++) a[i] = Abase[i * DH + k];
        float4 b0 = *(const float4*)(Ws + k * DH + tx * 8);
        float4 b1 = *(const float4*)(Ws + k * DH + tx * 8 + 4);
        float bb[8] = {b0.x, b0.y, b0.z, b0.w, b1.x, b1.y, b1.z, b1.w};
#pragma unroll
        for (int i = 0; i < 8; i++)
#pragma unroll
            for (int j = 0; j < 8; j++) acc[i][j] += a[i] * bb[j];
    }

    // epilogue: bias + leaky, store, (mode 1) column stats
    float bcol[8];
#pragma unroll
    for (int j = 0; j < 8; j++) bcol[j] = bias[tx * 8 + j];
    float ps[8], pq[8];
#pragma unroll
    for (int j = 0; j < 8; j++) { ps[j] = 0.f; pq[j] = 0.f; }

#pragma unroll
    for (int i = 0; i < 8; i++) {
        int grow = row0 + ty * 8 + i;
        if (grow < M) {
            float o[8];
#pragma unroll
            for (int j = 0; j < 8; j++) {
                float v = leaky(acc[i][j] + bcol[j]);
                o[j] = v;
                if (mode == 1) { ps[j] += v; pq[j] += v * v; }
            }
            float4* op = (float4*)(out + (size_t)grow * DH + tx * 8);
            op[0] = make_float4(o[0], o[1], o[2], o[3]);
            op[1] = make_float4(o[4], o[5], o[6], o[7]);
        }
    }

    if (mode == 1) {
        __syncthreads();
#pragma unroll
        for (int j = 0; j < 8; j++) As[ty * DH + tx * 8 + j] = ps[j];
        __syncthreads();
        if (tid < DH) {
            float s = 0.f;
#pragma unroll
            for (int t = 0; t < 16; t++) s += As[t * DH + tid];
            atomicAdd(&gsum[tid], s);
        }
        __syncthreads();
#pragma unroll
        for (int j = 0; j < 8; j++) As[ty * DH + tx * 8 + j] = pq[j];
        __syncthreads();
        if (tid < DH) {
            float s = 0.f;
#pragma unroll
            for (int t = 0; t < 16; t++) s += As[t * DH + tid];
            atomicAdd(&gsq[tid], s);
        }
    }
}

// ---------------- sums -> folded BN affine ----------------
__global__ void bn_prep(const float* __restrict__ sum, const float* __restrict__ sumsq,
                        float n, const float* __restrict__ g, const float* __restrict__ b,
                        float* __restrict__ oa, float* __restrict__ oc, int D) {
    int c = threadIdx.x;
    if (c < D) {
        float m = sum[c] / n;
        float v = sumsq[c] / n - m * m;
        float r = rsqrtf(v + BN_EPS);
        oa[c] = g[c] * r;
        oc[c] = b[c] - g[c] * m * r;
    }
}

// ---------------- graph pooling: pooled[batch[n]] += x[n] ----------------
__global__ void __launch_bounds__(256) pool_kernel(const float* __restrict__ x,
                                                   const int* __restrict__ batch,
                                                   float* __restrict__ pooled, int n) {
    int node = blockIdx.x * 8 + (threadIdx.x >> 5);
    int lane = threadIdx.x & 31;
    if (node >= n) return;
    int b = __ldg(batch + node);
    float4 v = ((const float4*)(x + (size_t)node * DH))[lane];
    red_add_v4(pooled + (size_t)b * DH + lane * 4, v);
}

// ---------------- column mean/var over rows -> folded affine ----------------
__global__ void colstats(const float* __restrict__ data, int rows, int cols,
                         const float* __restrict__ g, const float* __restrict__ b,
                         float* __restrict__ oa, float* __restrict__ oc) {
    int col = blockIdx.x;
    int t = threadIdx.x;
    float s = 0.f, q = 0.f;
    for (int r = t; r < rows; r += blockDim.x) {
        float v = data[(size_t)r * cols + col];
        s += v; q += v * v;
    }
    __shared__ float ss[256], qq[256];
    ss[t] = s; qq[t] = q;
    __syncthreads();
    for (int off = 128; off > 0; off >>= 1) {
        if (t < off) { ss[t] += ss[t + off]; qq[t] += qq[t + off]; }
        __syncthreads();
    }
    if (t == 0) {
        float m = ss[0] / rows;
        float v = qq[0] / rows - m * m;
        float r = rsqrtf(v + BN_EPS);
        oa[col] = g[col] * r;
        oc[col] = b[col] - g[col] * m * r;
    }
}

// ---------------- head part 1: BN(pooled)@fcW+fcb, cond MLP, cat, leaky(cat@fW1+fb1) ----------------
__global__ void __launch_bounds__(64) head1(
    const float* __restrict__ pooled, const float* __restrict__ pa, const float* __restrict__ pc,
    const float* __restrict__ fcW, const float* __restrict__ fcb,
    const float* __restrict__ feats,
    const float* __restrict__ cW1, const float* __restrict__ cb1,
    const float* __restrict__ cW2, const float* __restrict__ cb2,
    const float* __restrict__ fW1, const float* __restrict__ fb1,
    float* __restrict__ h1out) {
    int g = blockIdx.x;
    int j = threadIdx.x;  // 0..63
    __shared__ float cat[DLAT + 8];

    // out64[j] = BN(pooled[g]) @ fcW + fcb
    float o = fcb[j];
    const float* pr = pooled + (size_t)g * DH;
    for (int k = 0; k < DH; k++) o += (pr[k] * pa[k] + pc[k]) * fcW[k * DLAT + j];
    cat[j] = o;

    if (j < 8) {
        float c1[8];
#pragma unroll
        for (int i = 0; i < 8; i++) {
            float a = cb1[i];
#pragma unroll
            for (int m = 0; m < NCOND; m++) a += feats[g * NCOND + m] * cW1[m * 8 + i];
            c1[i] = fmaxf(a, 0.f);
        }
        float o2 = cb2[j];
#pragma unroll
        for (int i = 0; i < 8; i++) o2 += c1[i] * cW2[i * 8 + j];
        cat[DLAT + j] = o2;
    }
    __syncthreads();

    float h = fb1[j];
    for (int k = 0; k < DLAT + 8; k++) h += cat[k] * fW1[k * DLAT + j];
    h1out[(size_t)g * DLAT + j] = leaky(h);
}

// ---------------- head part 2: out = BN(h1) @ fW2 + fb2 ----------------
__global__ void __launch_bounds__(64) head2(
    const float* __restrict__ h1, const float* __restrict__ fa, const float* __restrict__ fc,
    const float* __restrict__ fW2, const float* __restrict__ fb2,
    float* __restrict__ out) {
    int g = blockIdx.x;
    int j = threadIdx.x;
    __shared__ float hn[DLAT];
    hn[j] = h1[(size_t)g * DLAT + j] * fa[j] + fc[j];
    __syncthreads();
    float o = fb2[j];
    for (int k = 0; k < DLAT; k++) o += hn[k] * fW2[k * DLAT + j];
    out[(size_t)g * DLAT + j] = o;
}

// ---------------- launch ----------------
extern "C" void kernel_launch(void* const* d_in, const int* in_sizes, int n_in,
                              void* d_out, int out_size) {
    const float* x      = (const float*)d_in[0];
    const int*   ei     = (const int*)d_in[1];
    const int*   batch  = (const int*)d_in[2];
    const float* feats  = (const float*)d_in[3];
    const float* convW1 = (const float*)d_in[4];
    const float* convb1 = (const float*)d_in[5];
    const float* convg1 = (const float*)d_in[6];
    const float* convbb1= (const float*)d_in[7];
    const float* convW2 = (const float*)d_in[8];
    const float* convb2 = (const float*)d_in[9];
    const float* bng    = (const float*)d_in[10];
    const float* bnb    = (const float*)d_in[11];
    const float* fcW    = (const float*)d_in[12];
    const float* fcb    = (const float*)d_in[13];
    const float* cW1    = (const float*)d_in[14];
    const float* cb1    = (const float*)d_in[15];
    const float* cW2    = (const float*)d_in[16];
    const float* cb2    = (const float*)d_in[17];
    const float* fW1    = (const float*)d_in[18];
    const float* fb1    = (const float*)d_in[19];
    const float* fg     = (const float*)d_in[20];
    const float* fb_    = (const float*)d_in[21];
    const float* fW2    = (const float*)d_in[22];
    const float* fb2    = (const float*)d_in[23];
    float* dout = (float*)d_out;

    int nE = in_sizes[1] / 2;
    const int* src = ei;
    const int* dst = ei + nE;
    int M = in_sizes[0] / DH;
    int G = in_sizes[3] / NCOND;

    float *p_agg, *p_h, *p_x, *p_sum, *p_sq, *p_a, *p_c, *p_pool, *p_pa, *p_pc, *p_h1, *p_fa, *p_fc;
    cudaGetSymbolAddress((void**)&p_agg, g_agg);
    cudaGetSymbolAddress((void**)&p_h, g_h);
    cudaGetSymbolAddress((void**)&p_x, g_x);
    cudaGetSymbolAddress((void**)&p_sum, g_sum);
    cudaGetSymbolAddress((void**)&p_sq, g_sumsq);
    cudaGetSymbolAddress((void**)&p_a, g_a);
    cudaGetSymbolAddress((void**)&p_c, g_c);
    cudaGetSymbolAddress((void**)&p_pool, g_pooled);
    cudaGetSymbolAddress((void**)&p_pa, g_pa);
    cudaGetSymbolAddress((void**)&p_pc, g_pc);
    cudaGetSymbolAddress((void**)&p_h1, g_h1);
    cudaGetSymbolAddress((void**)&p_fa, g_fa);
    cudaGetSymbolAddress((void**)&p_fc, g_fc);

    cudaFuncSetAttribute(gemm_fused, cudaFuncAttributeMaxDynamicSharedMemorySize, 131072);

    int gemmGrid = (M + 127) / 128;
    int aggN4 = N_NODES * DH / 4;

    const float* xcur = x;
    for (int l = 0; l < 3; l++) {
        zerok<<<(aggN4 + 255) / 256, 256>>>((float4*)p_agg, aggN4);
        zerok<<<1, 64>>>((float4*)p_sum, DH / 4);
        zerok<<<1, 64>>>((float4*)p_sq, DH / 4);
        edge_agg<<<(nE + 7) / 8, 256>>>(xcur, src, dst, p_agg, nE);
        gemm_fused<<<gemmGrid, 256, 131072>>>(xcur, p_agg, convW1 + (size_t)l * DH * DH,
                                              convb1 + l * DH, nullptr, nullptr,
                                              p_h, p_sum, p_sq, M, 1);
        bn_prep<<<1, DH>>>(p_sum, p_sq, (float)M, convg1 + l * DH, convbb1 + l * DH, p_a, p_c, DH);
        gemm_fused<<<gemmGrid, 256, 131072>>>(p_h, nullptr, convW2 + (size_t)l * DH * DH,
                                              convb2 + l * DH, p_a, p_c,
                                              p_x, nullptr, nullptr, M, 2);
        xcur = p_x;
    }

    int poolN4 = N_GRAPHS * DH / 4;
    zerok<<<(poolN4 + 255) / 256, 256>>>((float4*)p_pool, poolN4);
    pool_kernel<<<(M + 7) / 8, 256>>>(xcur, batch, p_pool, M);
    colstats<<<DH, 256>>>(p_pool, G, DH, bng, bnb, p_pa, p_pc);
    head1<<<G, 64>>>(p_pool, p_pa, p_pc, fcW, fcb, feats, cW1, cb1, cW2, cb2, fW1, fb1, p_h1);
    colstats<<<DLAT, 256>>>(p_h1, G, DLAT, fg, fb_, p_fa, p_fc);
    head2<<<G, 64>>>(p_h1, p_fa, p_fc, fW2, fb2, dout);
}

// round 3
// speedup vs baseline: 1.7656x; 1.7656x over previous
#include <cuda_runtime.h>
#include <cstdint>

#define N_NODES 100000
#define N_EDGESC 1600000
#define N_GRAPHS 512
#define DH 128
#define DLAT 64
#define NCOND 7
#define BN_EPS 1e-5f

// ================= scratch (device globals; no allocation allowed) =================
__device__ float g_h[N_NODES * DH];     // gathered h (GEMM1 input)
__device__ float g_h2[N_NODES * DH];    // GEMM1 output
__device__ float g_x[N_NODES * DH];     // GEMM2 output (layer output)
__device__ uint4 g_Bpk[256 * 32];       // fragment-packed weights (hi/lo tf32)
__device__ float g_bias[DH];
__device__ int g_cnt[N_NODES];
__device__ int g_rowptr[N_NODES + 1];
__device__ int g_bsum[128];
__device__ int g_bscan[128];
__device__ int g_csr[N_EDGESC];
__device__ float g_sum[DH];
__device__ float g_sumsq[DH];
__device__ float g_a[DH];
__device__ float g_c[DH];
__device__ float g_pooled[N_GRAPHS * DH];
__device__ float g_pa[DH];
__device__ float g_pc[DH];
__device__ float g_h1[N_GRAPHS * DLAT];
__device__ float g_fa[DLAT];
__device__ float g_fc[DLAT];

// ================= helpers =================
__device__ __forceinline__ float leaky(float x) { return fmaxf(x, 0.2f * x); }
__device__ __forceinline__ void red_add_v4(float* p, float4 v) {
    asm volatile("red.global.add.v4.f32 [%0], {%1,%2,%3,%4};"
                 :: "l"(p), "f"(v.x), "f"(v.y), "f"(v.z), "f"(v.w) : "memory");
}
__device__ __forceinline__ uint32_t f2tf32(float x) {
    uint32_t r;
    asm("cvt.rna.tf32.f32 %0, %1;" : "=r"(r) : "f"(x));
    return r;
}
__device__ __forceinline__ void mma_tf32(float* d, uint32_t a0, uint32_t a1,
                                         uint32_t a2, uint32_t a3,
                                         uint32_t b0, uint32_t b1) {
    asm volatile(
        "mma.sync.aligned.m16n8k8.row.col.f32.tf32.tf32.f32 "
        "{%0,%1,%2,%3}, {%4,%5,%6,%7}, {%8,%9}, {%0,%1,%2,%3};"
        : "+f"(d[0]), "+f"(d[1]), "+f"(d[2]), "+f"(d[3])
        : "r"(a0), "r"(a1), "r"(a2), "r"(a3), "r"(b0), "r"(b1));
}

// ================= zero =================
__global__ void zerok(float4* p, int n4) {
    int i = blockIdx.x * blockDim.x + threadIdx.x;
    if (i < n4) p[i] = make_float4(0.f, 0.f, 0.f, 0.f);
}

// ================= CSR build =================
__global__ void hist_k(const int* __restrict__ dst, int* __restrict__ cnt, int nE) {
    int i = blockIdx.x * blockDim.x + threadIdx.x;
    if (i < nE) atomicAdd(&cnt[dst[i]], 1);
}
__global__ void scan_block(const int* __restrict__ cnt, int* __restrict__ excl,
                           int* __restrict__ bsum, int n) {
    __shared__ int sm[1024];
    int i = blockIdx.x * 1024 + threadIdx.x;
    int v = (i < n) ? cnt[i] : 0;
    sm[threadIdx.x] = v;
    __syncthreads();
    for (int off = 1; off < 1024; off <<= 1) {
        int t = (threadIdx.x >= off) ? sm[threadIdx.x - off] : 0;
        __syncthreads();
        sm[threadIdx.x] += t;
        __syncthreads();
    }
    if (i < n) excl[i] = sm[threadIdx.x] - v;
    if (threadIdx.x == 1023) bsum[blockIdx.x] = sm[1023];
}
__global__ void scan_sums(const int* __restrict__ bsum, int* __restrict__ bscan, int nb) {
    __shared__ int sm[128];
    int t = threadIdx.x;
    int v = (t < nb) ? bsum[t] : 0;
    sm[t] = v;
    __syncthreads();
    for (int off = 1; off < 128; off <<= 1) {
        int u = (t >= off) ? sm[t - off] : 0;
        __syncthreads();
        sm[t] += u;
        __syncthreads();
    }
    if (t < nb) bscan[t] = sm[t] - v;
}
__global__ void add_off(int* __restrict__ rowptr, const int* __restrict__ bscan,
                        int* __restrict__ cursor, int n, int nE) {
    int i = blockIdx.x * blockDim.x + threadIdx.x;
    if (i < n) {
        int v = rowptr[i] + bscan[i >> 10];
        rowptr[i] = v;
        cursor[i] = v;
    }
    if (i == 0) rowptr[n] = nE;
}
__global__ void scatter_k(const int* __restrict__ src, const int* __restrict__ dst,
                          int* __restrict__ cursor, int* __restrict__ csr, int nE) {
    int i = blockIdx.x * blockDim.x + threadIdx.x;
    if (i < nE) {
        int pos = atomicAdd(&cursor[dst[i]], 1);
        csr[pos] = src[i];
    }
}

// ================= gather: h = x[node] + sum_{nb in CSR} x[nb] =================
__global__ void __launch_bounds__(256) gather_f32(
    const float* __restrict__ x, const int* __restrict__ rowptr, const int* __restrict__ csr,
    float* __restrict__ h, int M) {
    int node = blockIdx.x * 8 + (threadIdx.x >> 5);
    if (node >= M) return;
    int lane = threadIdx.x & 31;
    const float4* xv = (const float4*)x;
    float4 acc = __ldg(xv + (size_t)node * 32 + lane);
    int e0 = __ldg(rowptr + node), e1 = __ldg(rowptr + node + 1);
    int e = e0;
    for (; e + 4 <= e1; e += 4) {
        int s0 = __ldg(csr + e), s1 = __ldg(csr + e + 1);
        int s2 = __ldg(csr + e + 2), s3 = __ldg(csr + e + 3);
        float4 v0 = __ldg(xv + (size_t)s0 * 32 + lane);
        float4 v1 = __ldg(xv + (size_t)s1 * 32 + lane);
        float4 v2 = __ldg(xv + (size_t)s2 * 32 + lane);
        float4 v3 = __ldg(xv + (size_t)s3 * 32 + lane);
        acc.x += v0.x + v1.x + v2.x + v3.x;
        acc.y += v0.y + v1.y + v2.y + v3.y;
        acc.z += v0.z + v1.z + v2.z + v3.z;
        acc.w += v0.w + v1.w + v2.w + v3.w;
    }
    for (; e < e1; e++) {
        int s = __ldg(csr + e);
        float4 v = __ldg(xv + (size_t)s * 32 + lane);
        acc.x += v.x; acc.y += v.y; acc.z += v.z; acc.w += v.w;
    }
    ((float4*)(h + (size_t)node * DH))[lane] = acc;
}

// ================= weight prep: fragment-packed tf32 hi/lo with optional BN fold =================
// Bpk layout: [kstep 16][tile 16][lane 32] uint4 = (hi(w@k), lo(w@k), hi(w@k+4), lo(w@k+4))
// where k = kstep*8 + lane%4, n = tile*8 + lane/4, w = a[k]*W[k][n]
__global__ void __launch_bounds__(32) wprep_frag(
    const float* __restrict__ W, const float* __restrict__ a,
    uint4* __restrict__ Bpk, int hasAff) {
    int pos = blockIdx.x;     // 0..255
    int lane = threadIdx.x;   // 0..31
    int ks = pos >> 4, t = pos & 15;
    int k0 = ks * 8 + (lane & 3);
    int n = t * 8 + (lane >> 2);
    float w0 = W[k0 * DH + n];
    float w1 = W[(k0 + 4) * DH + n];
    if (hasAff) { w0 *= a[k0]; w1 *= a[k0 + 4]; }
    uint32_t h0 = f2tf32(w0);
    uint32_t h1 = f2tf32(w1);
    uint32_t l0 = f2tf32(w0 - __uint_as_float(h0));
    uint32_t l1 = f2tf32(w1 - __uint_as_float(h1));
    Bpk[pos * 32 + lane] = make_uint4(h0, l0, h1, l1);
}

// bias fold: bout[n] = b[n] + sum_k c[k]*W[k][n]
__global__ void __launch_bounds__(128) bias_fold(
    const float* __restrict__ W, const float* __restrict__ b,
    const float* __restrict__ c, float* __restrict__ bout, int hasAff) {
    int n = blockIdx.x, k = threadIdx.x;
    __shared__ float red[DH];
    red[k] = hasAff ? c[k] * W[k * DH + n] : 0.f;
    __syncthreads();
    for (int off = 64; off > 0; off >>= 1) {
        if (k < off) red[k] += red[k + off];
        __syncthreads();
    }
    if (k == 0) bout[n] = b[n] + red[0];
}

// ================= 3xTF32 GEMM: out = leaky(A @ Wpacked + bias), 128x128 tile =================
#define AS_STRIDE 132
#define SM_B_OFF 67584
#define SM_BIAS_OFF 198656
#define GEMM_SMEM 199168

__global__ void __launch_bounds__(256, 1) gemm_tc(
    const float4* __restrict__ A, const uint4* __restrict__ Bpk,
    const float* __restrict__ bias, float* __restrict__ out, int M) {
    extern __shared__ char smem[];
    float* As = (float*)smem;                         // 128 x 132 fp32
    uint4* Bs = (uint4*)(smem + SM_B_OFF);            // 256 x 32 uint4
    float* sb = (float*)(smem + SM_BIAS_OFF);         // 128 fp32
    int tid = threadIdx.x;
    int row0 = blockIdx.x << 7;

    if (tid < 128) sb[tid] = bias[tid];
#pragma unroll
    for (int it = 0; it < 16; it++) {
        int idx = it * 256 + tid;
        int r = idx >> 5, c4 = idx & 31;
        int gr = row0 + r;
        float4 v = make_float4(0.f, 0.f, 0.f, 0.f);
        if (gr < M) v = __ldg(A + (size_t)gr * 32 + c4);
        *(float4*)(As + r * AS_STRIDE + c4 * 4) = v;
    }
#pragma unroll
    for (int it = 0; it < 32; it++) Bs[it * 256 + tid] = __ldg(Bpk + it * 256 + tid);
    __syncthreads();

    int warp = tid >> 5, lane = tid & 31;
    int m0 = warp * 16;
    int gid = lane >> 2, qid = lane & 3;

    float acc[16][4];
#pragma unroll
    for (int t = 0; t < 16; t++)
#pragma unroll
        for (int j = 0; j < 4; j++) acc[t][j] = 0.f;

    const float* arow0 = As + (m0 + gid) * AS_STRIDE;
    const float* arow1 = As + (m0 + gid + 8) * AS_STRIDE;

#pragma unroll
    for (int ks = 0; ks < 16; ks++) {
        int kb = ks * 8 + qid;
        float a0 = arow0[kb], a1 = arow1[kb];
        float a2 = arow0[kb + 4], a3 = arow1[kb + 4];
        uint32_t ah0 = f2tf32(a0), ah1 = f2tf32(a1), ah2 = f2tf32(a2), ah3 = f2tf32(a3);
        uint32_t al0 = f2tf32(a0 - __uint_as_float(ah0));
        uint32_t al1 = f2tf32(a1 - __uint_as_float(ah1));
        uint32_t al2 = f2tf32(a2 - __uint_as_float(ah2));
        uint32_t al3 = f2tf32(a3 - __uint_as_float(ah3));
        const uint4* bp = Bs + ks * 512 + lane;
#pragma unroll
        for (int t = 0; t < 16; t++) {
            uint4 bv = bp[t * 32];
            mma_tf32(acc[t], ah0, ah1, ah2, ah3, bv.x, bv.z);  // ah*bh
            mma_tf32(acc[t], ah0, ah1, ah2, ah3, bv.y, bv.w);  // ah*bl
            mma_tf32(acc[t], al0, al1, al2, al3, bv.x, bv.z);  // al*bh
        }
    }

    int r0 = row0 + m0 + gid;
    int r1 = r0 + 8;
#pragma unroll
    for (int t = 0; t < 16; t++) {
        int c = t * 8 + qid * 2;
        float b0 = sb[c], b1 = sb[c + 1];
        if (r0 < M)
            *(float2*)(out + (size_t)r0 * DH + c) =
                make_float2(leaky(acc[t][0] + b0), leaky(acc[t][1] + b1));
        if (r1 < M)
            *(float2*)(out + (size_t)r1 * DH + c) =
                make_float2(leaky(acc[t][2] + b0), leaky(acc[t][3] + b1));
    }
}

// ================= column stats (fp32, big M) =================
__global__ void __launch_bounds__(256) colstats_f32(
    const float4* __restrict__ h, float* __restrict__ sum, float* __restrict__ sq, int M) {
    int c4 = threadIdx.x & 31;
    int rs = threadIdx.x >> 5;  // 0..7
    float4 s = make_float4(0, 0, 0, 0), q = make_float4(0, 0, 0, 0);
    for (int r = blockIdx.x * 8 + rs; r < M; r += gridDim.x * 8) {
        float4 v = __ldg(h + (size_t)r * 32 + c4);
        s.x += v.x; s.y += v.y; s.z += v.z; s.w += v.w;
        q.x += v.x * v.x; q.y += v.y * v.y; q.z += v.z * v.z; q.w += v.w * v.w;
    }
    __shared__ float4 sbuf[8][32], qbuf[8][32];
    sbuf[rs][c4] = s; qbuf[rs][c4] = q;
    __syncthreads();
    if (threadIdx.x < 32) {
        int t = threadIdx.x;
        float4 S = sbuf[0][t], Q = qbuf[0][t];
#pragma unroll
        for (int k = 1; k < 8; k++) {
            float4 a = sbuf[k][t], b = qbuf[k][t];
            S.x += a.x; S.y += a.y; S.z += a.z; S.w += a.w;
            Q.x += b.x; Q.y += b.y; Q.z += b.z; Q.w += b.w;
        }
        atomicAdd(&sum[4 * t], S.x); atomicAdd(&sum[4 * t + 1], S.y);
        atomicAdd(&sum[4 * t + 2], S.z); atomicAdd(&sum[4 * t + 3], S.w);
        atomicAdd(&sq[4 * t], Q.x); atomicAdd(&sq[4 * t + 1], Q.y);
        atomicAdd(&sq[4 * t + 2], Q.z); atomicAdd(&sq[4 * t + 3], Q.w);
    }
}

// ================= sums -> folded BN affine =================
__global__ void bn_prep(const float* __restrict__ sum, const float* __restrict__ sumsq,
                        float n, const float* __restrict__ g, const float* __restrict__ b,
                        float* __restrict__ oa, float* __restrict__ oc, int D) {
    int c = threadIdx.x;
    if (c < D) {
        float m = sum[c] / n;
        float v = sumsq[c] / n - m * m;
        float r = rsqrtf(v + BN_EPS);
        oa[c] = g[c] * r;
        oc[c] = b[c] - g[c] * m * r;
    }
}

// ================= pooling =================
__global__ void __launch_bounds__(256) pool_kernel(const float* __restrict__ x,
                                                   const int* __restrict__ batch,
                                                   float* __restrict__ pooled, int n) {
    int node = blockIdx.x * 8 + (threadIdx.x >> 5);
    int lane = threadIdx.x & 31;
    if (node >= n) return;
    int b = __ldg(batch + node);
    float4 v = ((const float4*)(x + (size_t)node * DH))[lane];
    red_add_v4(pooled + (size_t)b * DH + lane * 4, v);
}

// ================= small column stats (pooled / h1) =================
__global__ void colstats(const float* __restrict__ data, int rows, int cols,
                         const float* __restrict__ g, const float* __restrict__ b,
                         float* __restrict__ oa, float* __restrict__ oc) {
    int col = blockIdx.x;
    int t = threadIdx.x;
    float s = 0.f, q = 0.f;
    for (int r = t; r < rows; r += blockDim.x) {
        float v = data[(size_t)r * cols + col];
        s += v; q += v * v;
    }
    __shared__ float ss[256], qq[256];
    ss[t] = s; qq[t] = q;
    __syncthreads();
    for (int off = 128; off > 0; off >>= 1) {
        if (t < off) { ss[t] += ss[t + off]; qq[t] += qq[t + off]; }
        __syncthreads();
    }
    if (t == 0) {
        float m = ss[0] / rows;
        float v = qq[0] / rows - m * m;
        float r = rsqrtf(v + BN_EPS);
        oa[col] = g[col] * r;
        oc[col] = b[col] - g[col] * m * r;
    }
}

// ================= head =================
__global__ void __launch_bounds__(64) head1(
    const float* __restrict__ pooled, const float* __restrict__ pa, const float* __restrict__ pc,
    const float* __restrict__ fcW, const float* __restrict__ fcb,
    const float* __restrict__ feats,
    const float* __restrict__ cW1, const float* __restrict__ cb1,
    const float* __restrict__ cW2, const float* __restrict__ cb2,
    const float* __restrict__ fW1, const float* __restrict__ fb1,
    float* __restrict__ h1out) {
    int g = blockIdx.x;
    int j = threadIdx.x;
    __shared__ float cat[DLAT + 8];
    float o = fcb[j];
    const float* pr = pooled + (size_t)g * DH;
    for (int k = 0; k < DH; k++) o += (pr[k] * pa[k] + pc[k]) * fcW[k * DLAT + j];
    cat[j] = o;
    if (j < 8) {
        float c1[8];
#pragma unroll
        for (int i = 0; i < 8; i++) {
            float a = cb1[i];
#pragma unroll
            for (int m = 0; m < NCOND; m++) a += feats[g * NCOND + m] * cW1[m * 8 + i];
            c1[i] = fmaxf(a, 0.f);
        }
        float o2 = cb2[j];
#pragma unroll
        for (int i = 0; i < 8; i++) o2 += c1[i] * cW2[i * 8 + j];
        cat[DLAT + j] = o2;
    }
    __syncthreads();
    float h = fb1[j];
    for (int k = 0; k < DLAT + 8; k++) h += cat[k] * fW1[k * DLAT + j];
    h1out[(size_t)g * DLAT + j] = leaky(h);
}

__global__ void __launch_bounds__(64) head2(
    const float* __restrict__ h1, const float* __restrict__ fa, const float* __restrict__ fc,
    const float* __restrict__ fW2, const float* __restrict__ fb2,
    float* __restrict__ out) {
    int g = blockIdx.x;
    int j = threadIdx.x;
    __shared__ float hn[DLAT];
    hn[j] = h1[(size_t)g * DLAT + j] * fa[j] + fc[j];
    __syncthreads();
    float o = fb2[j];
    for (int k = 0; k < DLAT; k++) o += hn[k] * fW2[k * DLAT + j];
    out[(size_t)g * DLAT + j] = o;
}

// ================= launch =================
extern "C" void kernel_launch(void* const* d_in, const int* in_sizes, int n_in,
                              void* d_out, int out_size) {
    const float* x      = (const float*)d_in[0];
    const int*   ei     = (const int*)d_in[1];
    const int*   batch  = (const int*)d_in[2];
    const float* feats  = (const float*)d_in[3];
    const float* convW1 = (const float*)d_in[4];
    const float* convb1 = (const float*)d_in[5];
    const float* convg1 = (const float*)d_in[6];
    const float* convbb1= (const float*)d_in[7];
    const float* convW2 = (const float*)d_in[8];
    const float* convb2 = (const float*)d_in[9];
    const float* bng    = (const float*)d_in[10];
    const float* bnb    = (const float*)d_in[11];
    const float* fcW    = (const float*)d_in[12];
    const float* fcb    = (const float*)d_in[13];
    const float* cW1    = (const float*)d_in[14];
    const float* cb1    = (const float*)d_in[15];
    const float* cW2    = (const float*)d_in[16];
    const float* cb2    = (const float*)d_in[17];
    const float* fW1    = (const float*)d_in[18];
    const float* fb1    = (const float*)d_in[19];
    const float* fg     = (const float*)d_in[20];
    const float* fb_    = (const float*)d_in[21];
    const float* fW2    = (const float*)d_in[22];
    const float* fb2    = (const float*)d_in[23];
    float* dout = (float*)d_out;

    int nE = in_sizes[1] / 2;
    const int* src = ei;
    const int* dst = ei + nE;
    int M = in_sizes[0] / DH;
    int G = in_sizes[3] / NCOND;

    float *p_h, *p_h2, *p_x, *p_bias, *p_sum, *p_sq, *p_a, *p_c;
    float *p_pool, *p_pa, *p_pc, *p_h1, *p_fa, *p_fc;
    uint4* p_Bpk;
    int *p_cnt, *p_rowptr, *p_bsum, *p_bscan, *p_csr;
    cudaGetSymbolAddress((void**)&p_h, g_h);
    cudaGetSymbolAddress((void**)&p_h2, g_h2);
    cudaGetSymbolAddress((void**)&p_x, g_x);
    cudaGetSymbolAddress((void**)&p_Bpk, g_Bpk);
    cudaGetSymbolAddress((void**)&p_bias, g_bias);
    cudaGetSymbolAddress((void**)&p_cnt, g_cnt);
    cudaGetSymbolAddress((void**)&p_rowptr, g_rowptr);
    cudaGetSymbolAddress((void**)&p_bsum, g_bsum);
    cudaGetSymbolAddress((void**)&p_bscan, g_bscan);
    cudaGetSymbolAddress((void**)&p_csr, g_csr);
    cudaGetSymbolAddress((void**)&p_sum, g_sum);
    cudaGetSymbolAddress((void**)&p_sq, g_sumsq);
    cudaGetSymbolAddress((void**)&p_a, g_a);
    cudaGetSymbolAddress((void**)&p_c, g_c);
    cudaGetSymbolAddress((void**)&p_pool, g_pooled);
    cudaGetSymbolAddress((void**)&p_pa, g_pa);
    cudaGetSymbolAddress((void**)&p_pc, g_pc);
    cudaGetSymbolAddress((void**)&p_h1, g_h1);
    cudaGetSymbolAddress((void**)&p_fa, g_fa);
    cudaGetSymbolAddress((void**)&p_fc, g_fc);

    cudaFuncSetAttribute(gemm_tc, cudaFuncAttributeMaxDynamicSharedMemorySize, GEMM_SMEM);

    // ---- CSR build ----
    zerok<<<(N_NODES / 4 + 255) / 256, 256>>>((float4*)p_cnt, N_NODES / 4);
    hist_k<<<(nE + 255) / 256, 256>>>(dst, p_cnt, nE);
    int nb = (M + 1023) / 1024;
    scan_block<<<nb, 1024>>>(p_cnt, p_rowptr, p_bsum, M);
    scan_sums<<<1, 128>>>(p_bsum, p_bscan, nb);
    add_off<<<(M + 255) / 256, 256>>>(p_rowptr, p_bscan, p_cnt, M, nE);
    scatter_k<<<(nE + 255) / 256, 256>>>(src, dst, p_cnt, p_csr, nE);

    int gemmGrid = (M + 127) / 128;
    const float* xcur = x;
    for (int l = 0; l < 3; l++) {
        gather_f32<<<(M + 7) / 8, 256>>>(xcur, p_rowptr, p_csr, p_h, M);
        wprep_frag<<<256, 32>>>(convW1 + (size_t)l * DH * DH, nullptr, p_Bpk, 0);
        bias_fold<<<DH, DH>>>(convW1 + (size_t)l * DH * DH, convb1 + l * DH, nullptr, p_bias, 0);
        gemm_tc<<<gemmGrid, 256, GEMM_SMEM>>>((const float4*)p_h, p_Bpk, p_bias, p_h2, M);
        zerok<<<1, 64>>>((float4*)p_sum, DH / 4);
        zerok<<<1, 64>>>((float4*)p_sq, DH / 4);
        colstats_f32<<<256, 256>>>((const float4*)p_h2, p_sum, p_sq, M);
        bn_prep<<<1, DH>>>(p_sum, p_sq, (float)M, convg1 + l * DH, convbb1 + l * DH, p_a, p_c, DH);
        wprep_frag<<<256, 32>>>(convW2 + (size_t)l * DH * DH, p_a, p_Bpk, 1);
        bias_fold<<<DH, DH>>>(convW2 + (size_t)l * DH * DH, convb2 + l * DH, p_c, p_bias, 1);
        gemm_tc<<<gemmGrid, 256, GEMM_SMEM>>>((const float4*)p_h2, p_Bpk, p_bias, p_x, M);
        xcur = p_x;
    }

    int poolN4 = N_GRAPHS * DH / 4;
    zerok<<<(poolN4 + 255) / 256, 256>>>((float4*)p_pool, poolN4);
    pool_kernel<<<(M + 7) / 8, 256>>>(xcur, batch, p_pool, M);
    colstats<<<DH, 256>>>(p_pool, G, DH, bng, bnb, p_pa, p_pc);
    head1<<<G, 64>>>(p_pool, p_pa, p_pc, fcW, fcb, feats, cW1, cb1, cW2, cb2, fW1, fb1, p_h1);
    colstats<<<DLAT, 256>>>(p_h1, G, DLAT, fg, fb_, p_fa, p_fc);
    head2<<<G, 64>>>(p_h1, p_fa, p_fc, fW2, fb2, dout);
}